// round 13
// baseline (speedup 1.0000x reference)
#include <cuda_runtime.h>
#include <cuda_bf16.h>
#include <cfloat>
#include <math.h>

#define CC   64
#define NP   9216      // 96*96 pixels / nodes
#define HS   24        // hsi spatial
#define KNN  5
#define NKNN (NP*KNN)  // 46080 knn edges
#define NEDG (NKNN+NP) // + self loops = 55296
#define NTILE 72       // column tiles of 128
#define NCAND (NTILE*8)  // 576 candidates per row

typedef unsigned long long ull;

// ------------------------- scratch (no alloc allowed) -----------------------
__device__ float g_hsi_up[CC*NP];   // [c][pix], also residual
__device__ float g_hfeat[NP*CC];    // [pix][c]
__device__ float g_mfeat[NP*CC];
__device__ __nv_bfloat16 g_hfeat_bf[NP*CC];
__device__ __nv_bfloat16 g_mfeat_bf[NP*CC];
__device__ float g_z[NP*CC];        // [node][c]
__device__ float g_numer[NP*CC];    // [node][c]
__device__ float g_fmap[CC*NP];     // [c][pix]
__device__ float g_up1[CC*NP];
__device__ float g_el[NP], g_er[NP], g_den[NP];
__device__ unsigned g_mx[NP];
__device__ int g_topk[NP*KNN];
__device__ float g_cv[NCAND*NP];    // candidate bf16-sim values, [cand][row]
__device__ int   g_ci[NCAND*NP];    // candidate col indices,     [cand][row]

// ------------------------------- helpers ------------------------------------
__device__ __forceinline__ unsigned fenc(float v) {
    unsigned u = __float_as_uint(v);
    return (u & 0x80000000u) ? ~u : (u | 0x80000000u);
}
__device__ __forceinline__ float fdec(unsigned e) {
    unsigned u = (e & 0x80000000u) ? (e ^ 0x80000000u) : ~e;
    return __uint_as_float(u);
}
__device__ __forceinline__ ull pk2(float a, float b) {
    ull d;
    asm("mov.b64 %0, {%1, %2};" : "=l"(d) : "f"(a), "f"(b));
    return d;
}
__device__ __forceinline__ ull dup2(float a) {
    ull d;
    asm("mov.b64 %0, {%1, %1};" : "=l"(d) : "f"(a));
    return d;
}
__device__ __forceinline__ void upk2(ull v, float &a, float &b) {
    asm("mov.b64 {%0, %1}, %2;" : "=f"(a), "=f"(b) : "l"(v));
}
__device__ __forceinline__ ull fma2(ull a, ull b, ull c) {
    ull d;
    asm("fma.rn.f32x2 %0, %1, %2, %3;" : "=l"(d) : "l"(a), "l"(b), "l"(c));
    return d;
}
__device__ __forceinline__ void ldsm4(unsigned &r0, unsigned &r1, unsigned &r2,
                                      unsigned &r3, unsigned addr) {
    asm volatile("ldmatrix.sync.aligned.m8n8.x4.shared.b16 {%0,%1,%2,%3}, [%4];"
                 : "=r"(r0), "=r"(r1), "=r"(r2), "=r"(r3) : "r"(addr));
}
__device__ __forceinline__ void mma_bf16(float *d, const unsigned *a,
                                         unsigned b0, unsigned b1) {
    asm volatile(
        "mma.sync.aligned.m16n8k16.row.col.f32.bf16.bf16.f32 "
        "{%0,%1,%2,%3}, {%4,%5,%6,%7}, {%8,%9}, {%0,%1,%2,%3};"
        : "+f"(d[0]), "+f"(d[1]), "+f"(d[2]), "+f"(d[3])
        : "r"(a[0]), "r"(a[1]), "r"(a[2]), "r"(a[3]), "r"(b0), "r"(b1));
}

// bicubic weights (torch a=-0.75, align_corners=False, border replicate)
__device__ __forceinline__ void bicw(int o, float *w, int *id, int n) {
    float x = (o + 0.5f) * 0.25f - 0.5f;
    float fi = floorf(x);
    int   i0 = (int)fi;
    float t  = x - fi;
#pragma unroll
    for (int k = 0; k < 4; ++k) {
        int off = k - 1;
        float d = fabsf(t - (float)off);
        float wv;
        if (d <= 1.f)      wv = (1.25f * d - 2.25f) * d * d + 1.f;
        else if (d < 2.f)  wv = ((-0.75f * d + 3.75f) * d - 6.f) * d + 3.f;
        else               wv = 0.f;
        int ii = i0 + off;
        ii = ii < 0 ? 0 : (ii > n - 1 ? n - 1 : ii);
        id[k] = ii; w[k] = wv;
    }
}

// ---------------- K1: bicubic x4 upsample hsi -> g_hsi_up -------------------
__global__ __launch_bounds__(256) void k_bicubic(const float *__restrict__ hsi) {
    int i = blockIdx.x * 256 + threadIdx.x;
    if (i >= CC * NP) return;
    int c = i / NP, p = i % NP, oy = p / 96, ox = p % 96;
    float wy[4], wx[4]; int iy[4], ix[4];
    bicw(oy, wy, iy, HS);
    bicw(ox, wx, ix, HS);
    const float *s = hsi + c * (HS * HS);
    float acc = 0.f;
#pragma unroll
    for (int a = 0; a < 4; ++a) {
        float r = 0.f;
#pragma unroll
        for (int b = 0; b < 4; ++b) r += wx[b] * s[iy[a] * HS + ix[b]];
        acc += wy[a] * r;
    }
    g_hsi_up[i] = acc;
}

// ---------------- K2: embed (2x conv1x1 + PReLU) + bf16 copy ----------------
__global__ __launch_bounds__(256) void k_embed(
    const float *__restrict__ msi, int flag,
    const float *__restrict__ Wa, const float *__restrict__ ba, const float *__restrict__ aa,
    const float *__restrict__ Wb, const float *__restrict__ bb, const float *__restrict__ ab)
{
    __shared__ float sWa[64*65], sWb[64*65], sx[16*65], smid[16*65];
    const float *in = flag ? msi : (const float*)g_hsi_up;
    float *feat = flag ? g_mfeat : g_hfeat;
    __nv_bfloat16 *featb = flag ? g_mfeat_bf : g_hfeat_bf;
    int tid = threadIdx.x;
    for (int i = tid; i < 4096; i += 256) {
        int o = i >> 6, c = i & 63;
        sWa[o*65+c] = Wa[i]; sWb[o*65+c] = Wb[i];
    }
    int pix0 = blockIdx.x * 16;
    for (int i = tid; i < 1024; i += 256) {
        int c = i >> 4, p = i & 15;
        sx[p*65+c] = in[c*NP + pix0 + p];
    }
    float A1 = aa[0], A2 = ab[0];
    int oc = tid & 63, pg = tid >> 6;
    float bA = ba[oc], bB = bb[oc];
    __syncthreads();
    float acc[4];
#pragma unroll
    for (int j = 0; j < 4; ++j) acc[j] = bA;
#pragma unroll 8
    for (int ic = 0; ic < 64; ++ic) {
        float w = sWa[oc*65+ic];
#pragma unroll
        for (int j = 0; j < 4; ++j) acc[j] += w * sx[(4*pg+j)*65+ic];
    }
#pragma unroll
    for (int j = 0; j < 4; ++j) {
        float v = acc[j]; v = v >= 0.f ? v : A1 * v;
        smid[(4*pg+j)*65+oc] = v;
    }
    __syncthreads();
#pragma unroll
    for (int j = 0; j < 4; ++j) acc[j] = bB;
#pragma unroll 8
    for (int ic = 0; ic < 64; ++ic) {
        float w = sWb[oc*65+ic];
#pragma unroll
        for (int j = 0; j < 4; ++j) acc[j] += w * smid[(4*pg+j)*65+ic];
    }
#pragma unroll
    for (int j = 0; j < 4; ++j) {
        float v = acc[j]; v = v >= 0.f ? v : A2 * v;
        feat[(pix0 + 4*pg + j)*64 + oc] = v;
        featb[(pix0 + 4*pg + j)*64 + oc] = __float2bfloat16(v);
    }
}

// ---- K3: bf16 tensor-core sim tiles + per-tile top-8 candidates per row ----
// grid (72, 144): x = col tile (128 cols), y = row tile (64 rows). 256 thr.
// warps: (w&3) -> row block of 16, (w>>2) -> col half of 64.
__global__ __launch_bounds__(256) void k_simc()
{
    __shared__ __align__(16) unsigned char pool[64*130*4];   // 33280 B
    __nv_bfloat16 *sa = (__nv_bfloat16*)pool;                // [64][72] bf16
    __nv_bfloat16 *sb = (__nv_bfloat16*)(pool + 9216);       // [128][72] bf16
    float *sd = (float*)pool;                                // [64][130] f32 (reuse)
    int tid = threadIdx.x;
    int row0 = blockIdx.y * 64, col0 = blockIdx.x * 128;

    for (int i = tid; i < 64*8; i += 256) {
        int r = i >> 3, q = i & 7;
        uint4 v = ((const uint4*)g_hfeat_bf)[(row0 + r)*8 + q];
        *(uint4*)(sa + r*72 + q*8) = v;
    }
    for (int i = tid; i < 128*8; i += 256) {
        int r = i >> 3, q = i & 7;
        uint4 v = ((const uint4*)g_mfeat_bf)[(col0 + r)*8 + q];
        *(uint4*)(sb + r*72 + q*8) = v;
    }
    __syncthreads();

    int w = tid >> 5, lane = tid & 31;
    int wr = (w & 3) * 16;
    int wc = (w >> 2) * 64;
    float acc[8][4];
#pragma unroll
    for (int n = 0; n < 8; ++n)
#pragma unroll
        for (int j = 0; j < 4; ++j) acc[n][j] = 0.f;

    unsigned sa_base = (unsigned)__cvta_generic_to_shared(sa);
    unsigned sb_base = (unsigned)__cvta_generic_to_shared(sb);
    int at_r = wr + (lane & 15), at_k = (lane >> 4) * 8;
    int bt_n = (lane >> 4) * 8 + (lane & 7), bt_k = ((lane >> 3) & 1) * 8;
#pragma unroll
    for (int ks = 0; ks < 4; ++ks) {
        unsigned A[4];
        ldsm4(A[0], A[1], A[2], A[3], sa_base + (at_r*72 + ks*16 + at_k)*2);
#pragma unroll
        for (int nb = 0; nb < 4; ++nb) {
            unsigned B0, B1, B2, B3;
            ldsm4(B0, B1, B2, B3,
                  sb_base + ((wc + nb*16 + bt_n)*72 + ks*16 + bt_k)*2);
            mma_bf16(acc[2*nb],     A, B0, B1);
            mma_bf16(acc[2*nb + 1], A, B2, B3);
        }
    }
    __syncthreads();
    // write D tile to smem [row][130]
    int grp = lane >> 2, tig = lane & 3;
#pragma unroll
    for (int nb = 0; nb < 8; ++nb) {
        int cb = wc + 8*nb + 2*tig;
        sd[(wr + grp)*130 + cb]     = acc[nb][0];
        sd[(wr + grp)*130 + cb + 1] = acc[nb][1];
        sd[(wr + grp + 8)*130 + cb]     = acc[nb][2];
        sd[(wr + grp + 8)*130 + cb + 1] = acc[nb][3];
    }
    __syncthreads();
    // per-row top-8 of the 128 cols (ascending col order; strict > keeps earliest)
    if (tid < 64) {
        float tv[8]; int ti[8];
#pragma unroll
        for (int s = 0; s < 8; ++s) { tv[s] = -FLT_MAX; ti[s] = 0x7fffffff; }
        const float *row = &sd[tid*130];
        for (int c = 0; c < 128; ++c) {
            float v = row[c];
            if (v > tv[7]) {
                tv[7] = v; ti[7] = col0 + c;
#pragma unroll
                for (int s = 7; s >= 1; --s)
                    if (tv[s] > tv[s-1]) {
                        float t = tv[s]; tv[s] = tv[s-1]; tv[s-1] = t;
                        int u = ti[s]; ti[s] = ti[s-1]; ti[s-1] = u;
                    }
            }
        }
        int r = row0 + tid;
#pragma unroll
        for (int s = 0; s < 8; ++s) {
            g_cv[(blockIdx.x*8 + s)*NP + r] = tv[s];
            g_ci[(blockIdx.x*8 + s)*NP + r] = ti[s];
        }
    }
}

// ---- K3b: per-row candidate reduce (bf16 top-16) + exact fp32 rescore ------
__global__ __launch_bounds__(256) void k_sel()
{
    int row = blockIdx.x * 256 + threadIdx.x;
    if (row >= NP) return;
    float cv[16]; int ci[16];
#pragma unroll
    for (int s = 0; s < 16; ++s) { cv[s] = -FLT_MAX; ci[s] = 0x7fffffff; }
    for (int t = 0; t < NCAND; ++t) {
        float v = g_cv[t*NP + row];
        int ix = g_ci[t*NP + row];
        if (v > cv[15] || (v == cv[15] && ix < ci[15])) {
            cv[15] = v; ci[15] = ix;
#pragma unroll
            for (int s = 15; s >= 1; --s)
                if (cv[s] > cv[s-1] || (cv[s] == cv[s-1] && ci[s] < ci[s-1])) {
                    float tt = cv[s]; cv[s] = cv[s-1]; cv[s-1] = tt;
                    int  uu = ci[s]; ci[s] = ci[s-1]; ci[s-1] = uu;
                }
        }
    }
    // exact fp32 rescore of the 16 candidates; pick top-5 (value desc, idx asc)
    float ar[64];
#pragma unroll
    for (int k = 0; k < 64; k += 4)
        *(float4*)&ar[k] = *(const float4*)&g_hfeat[row*64 + k];
    float bv[5]; int bi[5];
#pragma unroll
    for (int s = 0; s < 5; ++s) { bv[s] = -FLT_MAX; bi[s] = 0x7fffffff; }
#pragma unroll 1
    for (int t = 0; t < 16; ++t) {
        int ix = ci[t];
        const float *b = &g_mfeat[ix*64];
        float dot = 0.f;
#pragma unroll
        for (int k = 0; k < 64; ++k) dot += ar[k] * b[k];
        if (dot > bv[4] || (dot == bv[4] && ix < bi[4])) {
            bv[4] = dot; bi[4] = ix;
#pragma unroll
            for (int s = 4; s >= 1; --s)
                if (bv[s] > bv[s-1] || (bv[s] == bv[s-1] && bi[s] < bi[s-1])) {
                    float tt = bv[s]; bv[s] = bv[s-1]; bv[s-1] = tt;
                    int  uu = bi[s]; bi[s] = bi[s-1]; bi[s-1] = uu;
                }
        }
    }
#pragma unroll
    for (int s = 0; s < 5; ++s) g_topk[row*KNN + s] = bi[s];
}

// ---------------- K4: z = [hfeat|mfeat] @ Wg --------------------------------
__global__ __launch_bounds__(256) void k_z(const float *__restrict__ Wg)
{
    __shared__ float sWg[128*64];
    __shared__ float sx[16*130];
    int tid = threadIdx.x;
    for (int i = tid; i < 8192; i += 256) sWg[i] = Wg[i];
    int n0 = blockIdx.x * 16;
    for (int i = tid; i < 2048; i += 256) {
        int p = i >> 7, c = i & 127;
        float v = c < 64 ? g_hfeat[(n0+p)*64 + c] : g_mfeat[(n0+p)*64 + (c-64)];
        sx[p*130 + c] = v;
    }
    __syncthreads();
    int oc = tid & 63, pg = tid >> 6;
    float acc[4] = {0.f, 0.f, 0.f, 0.f};
#pragma unroll 8
    for (int ic = 0; ic < 128; ++ic) {
        float w = sWg[ic*64 + oc];
#pragma unroll
        for (int j = 0; j < 4; ++j) acc[j] += w * sx[(4*pg+j)*130 + ic];
    }
#pragma unroll
    for (int j = 0; j < 4; ++j) g_z[(n0 + 4*pg + j)*64 + oc] = acc[j];
}

// ---------------- K5: el/er per-node attention scores -----------------------
__global__ __launch_bounds__(256) void k_elr(const float *__restrict__ al,
                                             const float *__restrict__ ar)
{
    int wid = (blockIdx.x * 256 + threadIdx.x) >> 5;
    int lane = threadIdx.x & 31;
    if (wid >= NP) return;
    float z0 = g_z[wid*64 + lane], z1 = g_z[wid*64 + lane + 32];
    float tl = z0 * al[lane] + z1 * al[lane + 32];
    float tr = z0 * ar[lane] + z1 * ar[lane + 32];
#pragma unroll
    for (int o = 16; o > 0; o >>= 1) {
        tl += __shfl_down_sync(0xffffffffu, tl, o);
        tr += __shfl_down_sync(0xffffffffu, tr, o);
    }
    if (lane == 0) { g_el[wid] = tl; g_er[wid] = tr; }
}

// ---------------- K6: GAT edge softmax + aggregation ------------------------
__global__ __launch_bounds__(256) void k_gat_init()
{
    int i = blockIdx.x * 256 + threadIdx.x;
    if (i < NP*CC) g_numer[i] = 0.f;
    if (i < NP) { g_den[i] = 0.f; g_mx[i] = 0u; }
}

__global__ __launch_bounds__(256) void k_gat_max()
{
    int e = blockIdx.x * 256 + threadIdx.x;
    if (e >= NEDG) return;
    int s, d;
    if (e < NKNN) { s = e % NP; d = g_topk[e]; }
    else          { s = d = e - NKNN; }
    float x = g_el[s] + g_er[d];
    float lg = x >= 0.f ? x : 0.2f * x;
    atomicMax(&g_mx[d], fenc(lg));
}

__global__ __launch_bounds__(256) void k_gat_acc()
{
    int e = (blockIdx.x * 256 + threadIdx.x) >> 5;
    int lane = threadIdx.x & 31;
    if (e >= NEDG) return;
    int s, d;
    if (e < NKNN) { s = e % NP; d = g_topk[e]; }
    else          { s = d = e - NKNN; }
    float x = g_el[s] + g_er[d];
    float lg = x >= 0.f ? x : 0.2f * x;
    float ex = __expf(lg - fdec(g_mx[d]));
    if (lane == 0) atomicAdd(&g_den[d], ex);
    atomicAdd(&g_numer[d*64 + lane],      ex * g_z[s*64 + lane]);
    atomicAdd(&g_numer[d*64 + lane + 32], ex * g_z[s*64 + lane + 32]);
}

__global__ __launch_bounds__(256) void k_gat_fin(const float *__restrict__ bg)
{
    int i = blockIdx.x * 256 + threadIdx.x;
    if (i >= CC*NP) return;
    int c = i / NP, n = i % NP;
    g_fmap[i] = g_numer[n*64 + c] / g_den[n] + bg[c];
}

// ---------------- K7: conv3x3 + bias + PReLU (+ residual) -------------------
__global__ __launch_bounds__(256) void k_conv(
    const float *__restrict__ Kw, const float *__restrict__ bias,
    const float *__restrict__ alpha, float *__restrict__ dout, int sel)
{
    __shared__ float in_s[8*18*22];
    __shared__ float w_s[16*8*9];
    const float *in = sel ? (const float*)g_up1 : (const float*)g_fmap;
    float *out = sel ? dout : (float*)g_up1;
    int tid = threadIdx.x;
    int b = blockIdx.x;
    int x0 = (b % 6) * 16, y0 = ((b / 6) % 6) * 16, ocb = (b / 36) * 16;
    int oc = tid >> 4, g = tid & 15;
    ull acc2[8];
#pragma unroll
    for (int m = 0; m < 8; ++m) acc2[m] = 0ull;
    for (int ic0 = 0; ic0 < 64; ic0 += 8) {
        __syncthreads();
        for (int i = tid; i < 2592; i += 256) {
            int ii = i / 324, rem = i % 324, yy = rem / 18, xx = rem % 18;
            int y = y0 + yy - 1, x = x0 + xx - 1;
            float v = (y >= 0 && y < 96 && x >= 0 && x < 96) ? in[(ic0+ii)*NP + y*96 + x] : 0.f;
            in_s[ii*396 + yy*22 + xx] = v;
        }
        for (int i = tid; i < 1152; i += 256) {
            int o = i / 72, rem = i % 72;
            w_s[i] = Kw[(ocb + o)*576 + ic0*9 + rem];
        }
        __syncthreads();
#pragma unroll
        for (int ic = 0; ic < 8; ++ic) {
#pragma unroll
            for (int dy = 0; dy < 3; ++dy) {
                const float *row = &in_s[ic*396 + (g + dy)*22];
                ull P[9];
#pragma unroll
                for (int m = 0; m < 9; ++m) P[m] = *(const ull*)&row[2*m];
                ull O[8];
#pragma unroll
                for (int m = 0; m < 8; ++m) {
                    float lo, hi, lo2, hi2;
                    upk2(P[m], lo, hi); upk2(P[m+1], lo2, hi2);
                    O[m] = pk2(hi, lo2);
                }
                const float *wr = &w_s[oc*72 + ic*9 + dy*3];
                ull w0 = dup2(wr[0]);
                ull w1 = dup2(wr[1]);
                ull w2 = dup2(wr[2]);
#pragma unroll
                for (int m = 0; m < 8; ++m) {
                    acc2[m] = fma2(w0, P[m],   acc2[m]);
                    acc2[m] = fma2(w1, O[m],   acc2[m]);
                    acc2[m] = fma2(w2, P[m+1], acc2[m]);
                }
            }
        }
    }
    float bv = bias[ocb + oc], av = alpha[0];
    int ocg = ocb + oc;
#pragma unroll
    for (int m = 0; m < 8; ++m) {
        float v0, v1; upk2(acc2[m], v0, v1);
        v0 += bv; v1 += bv;
        v0 = v0 >= 0.f ? v0 : av * v0;
        v1 = v1 >= 0.f ? v1 : av * v1;
        int o = ocg*NP + (y0 + g)*96 + x0 + 2*m;
        if (sel) { v0 += g_hsi_up[o]; v1 += g_hsi_up[o+1]; }
        out[o] = v0; out[o+1] = v1;
    }
}

// ---------------------------------------------------------------------------
extern "C" void kernel_launch(void* const* d_in, const int* in_sizes, int n_in,
                              void* d_out, int out_size)
{
    const float *msi = (const float*)d_in[0];
    const float *hsi = (const float*)d_in[1];
    const float *W1a = (const float*)d_in[2],  *b1a = (const float*)d_in[3],  *a1a = (const float*)d_in[4];
    const float *W1b = (const float*)d_in[5],  *b1b = (const float*)d_in[6],  *a1b = (const float*)d_in[7];
    const float *W2a = (const float*)d_in[8],  *b2a = (const float*)d_in[9],  *a2a = (const float*)d_in[10];
    const float *W2b = (const float*)d_in[11], *b2b = (const float*)d_in[12], *a2b = (const float*)d_in[13];
    const float *Wg  = (const float*)d_in[14];
    const float *al  = (const float*)d_in[15], *ar = (const float*)d_in[16], *bg = (const float*)d_in[17];
    const float *Ku1 = (const float*)d_in[18], *bu1 = (const float*)d_in[19], *au1 = (const float*)d_in[20];
    const float *Ku2 = (const float*)d_in[21], *bu2 = (const float*)d_in[22], *au2 = (const float*)d_in[23];
    float *out = (float*)d_out;

    k_bicubic<<<2304, 256>>>(hsi);
    k_embed<<<576, 256>>>(msi, 0, W1a, b1a, a1a, W1b, b1b, a1b);   // hsi branch
    k_embed<<<576, 256>>>(msi, 1, W2a, b2a, a2a, W2b, b2b, a2b);   // msi branch
    k_simc<<<dim3(NTILE, 144), 256>>>();
    k_sel<<<36, 256>>>();
    k_z<<<576, 256>>>(Wg);
    k_elr<<<1152, 256>>>(al, ar);
    k_gat_init<<<2304, 256>>>();
    k_gat_max<<<216, 256>>>();
    k_gat_acc<<<6912, 256>>>();
    k_gat_fin<<<2304, 256>>>(bg);
    k_conv<<<144, 256>>>(Ku1, bu1, au1, out, 0);
    k_conv<<<144, 256>>>(Ku2, bu2, au2, out, 1);
}